// round 3
// baseline (speedup 1.0000x reference)
#include <cuda_runtime.h>

// Two-simplicial attention, B=2, S=2048, H=4, D=64, W1=W2=64 (A=C=65).
// 2 positions per CTA, 512 threads, packed-operand f32x2 GEMM phases.

constexpr int Bc = 2, Sc = 2048, Hc = 4, Dc = 64;
constexpr float SCALE_F = 0.125f;
constexpr int P = 2;
constexpr int NT = 512;

// ---- smem layout (floats) ----
constexpr int OFF_K1Q = 0;                        // [P][66][64]   q-folded k1
constexpr int OFF_K2P = 8448;                     // [34][67][2]   (d-pair, buffer col, d-parity)
constexpr int OFF_V1  = OFF_K2P + 34 * 134;       // [66][64]
constexpr int OFF_V2P = OFF_V1 + 66 * 64;         // [34][64][2]   (row-pair, d, row-parity)
constexpr int OFF_W   = OFF_V2P + 34 * 128;       // [P][72][68]   cols = buffer rows, pre-zeroed
constexpr int OFF_NP  = OFF_W + P * 72 * 68;      // [P][8][64]
constexpr int OFF_DEN = OFF_NP + P * 8 * 64;      // [P][8]
constexpr int SMEM_FLOATS = OFF_DEN + P * 8;
constexpr int SMEM_BYTES = SMEM_FLOATS * 4;       // ~129.7 KB

typedef unsigned long long ull;

__device__ __forceinline__ void ffma2(ull& acc, ull a, ull b) {
    asm("fma.rn.f32x2 %0, %1, %2, %0;" : "+l"(acc) : "l"(a), "l"(b));
}
__device__ __forceinline__ float2 unpack2(ull v) {
    float2 f;
    asm("mov.b64 {%0, %1}, %2;" : "=f"(f.x), "=f"(f.y) : "l"(v));
    return f;
}

__global__ void __launch_bounds__(NT, 1)
tsa_kernel(const float* __restrict__ q,
           const float* __restrict__ k1,
           const float* __restrict__ k2,
           const float* __restrict__ v1,
           const float* __restrict__ v2,
           float* __restrict__ out) {
    extern __shared__ float sm[];
    const int tid = threadIdx.x;
    const int bid = blockIdx.x;
    const int h  = bid & 3;
    const int st = (bid >> 2) & 1023;
    const int b  = bid >> 12;
    const int s0 = st * 2;

    // ================= stage A: loads =================
    // zero W (phase 4 runs unguarded over 72 rows x 68 cols)
    for (int i = tid; i < P * 72 * 68 / 4; i += NT)
        *(float4*)&sm[OFF_W + i * 4] = make_float4(0.f, 0.f, 0.f, 0.f);
    // zero V2P tail pair (buffer rows 66,67)
    if (tid < 32)
        *(float4*)&sm[OFF_V2P + 33 * 128 + tid * 4] = make_float4(0.f, 0.f, 0.f, 0.f);

    // window rows r=0..65 -> global g = clamp(s0-64+r, 0)
    for (int i = tid; i < 66 * 16; i += NT) {
        int r = i >> 4, dq = i & 15;
        int g = s0 - 64 + r; if (g < 0) g = 0;
        int off = ((b * Sc + g) * Hc + h) * Dc + dq * 4;
        *(float4*)&sm[OFF_V1 + r * 64 + dq * 4] = *(const float4*)&v1[off];

        float4 bv = *(const float4*)&v2[off];
        {   // V2P[rp][d][par]
            int rp = r >> 1, par = r & 1;
            float* vp = &sm[OFF_V2P + rp * 128 + dq * 8 + par];
            vp[0] = bv.x; vp[2] = bv.y; vp[4] = bv.z; vp[6] = bv.w;
        }
        float4 cv = *(const float4*)&k2[off];
        {   // K2P[dp][col][par]
            int dp0 = dq * 2;
            *(float2*)&sm[OFF_K2P + dp0 * 134 + r * 2]       = make_float2(cv.x, cv.y);
            *(float2*)&sm[OFF_K2P + (dp0 + 1) * 134 + r * 2] = make_float2(cv.z, cv.w);
        }
    }
    // q-folded k1 per position
    for (int i = tid; i < P * 66 * 16; i += NT) {
        int p = i / (66 * 16);
        int rr = i - p * 66 * 16;
        int r = rr >> 4, dq = rr & 15;
        int g = s0 - 64 + r; if (g < 0) g = 0;
        int off  = ((b * Sc + g) * Hc + h) * Dc + dq * 4;
        int qoff = ((b * Sc + s0 + p) * Hc + h) * Dc + dq * 4;
        float4 kv = *(const float4*)&k1[off];
        float4 qv = *(const float4*)&q[qoff];
        kv.x *= qv.x; kv.y *= qv.y; kv.z *= qv.z; kv.w *= qv.w;
        *(float4*)&sm[OFF_K1Q + (p * 66 + r) * 64 + dq * 4] = kv;
    }
    __syncthreads();

    // ================= phase 3: scores + exp =================
    const int wid = tid >> 5, lane = tid & 31;
    const int p  = wid >> 3;
    const int wa = wid & 7;
    const int a0 = wa * 9;
    const int sp = s0 + p;
    const int amin = 64 - sp;
    const float* k1q = &sm[OFF_K1Q + p * 66 * 64];
    float* sW = &sm[OFF_W + p * 72 * 68];

    int rowi[9];
#pragma unroll
    for (int i = 0; i < 9; i++) {
        int r = p + a0 + i;
        rowi[i] = (r > 65) ? 65 : r;
    }

    ull acc[9][2];
#pragma unroll
    for (int i = 0; i < 9; i++) { acc[i][0] = 0ull; acc[i][1] = 0ull; }

    const float* c0p = &sm[OFF_K2P + (p + lane) * 2];
    const float* c1p = c0p + 64;   // col p+lane+32

    ull n00 = *(const ull*)(c0p);
    ull n10 = *(const ull*)(c0p + 134);
    ull n01 = *(const ull*)(c1p);
    ull n11 = *(const ull*)(c1p + 134);

#pragma unroll 4
    for (int dq = 0; dq < 16; dq++) {
        ull cur00 = n00, cur10 = n10, cur01 = n01, cur11 = n11;
        int nx = (dq + 1) * 268;         // next quad: 2 d-pairs * 134
        n00 = *(const ull*)(c0p + nx);
        n10 = *(const ull*)(c0p + nx + 134);
        n01 = *(const ull*)(c1p + nx);
        n11 = *(const ull*)(c1p + nx + 134);
#pragma unroll
        for (int i = 0; i < 9; i++) {
            ulonglong2 a4 = *(const ulonglong2*)&k1q[rowi[i] * 64 + dq * 4];
            ffma2(acc[i][0], a4.x, cur00);
            ffma2(acc[i][1], a4.x, cur01);
            ffma2(acc[i][0], a4.y, cur10);
            ffma2(acc[i][1], a4.y, cur11);
        }
    }

    float dloc = 0.0f;
#pragma unroll
    for (int i = 0; i < 9; i++) {
        int a = a0 + i;
        bool av = (a < 65) && (a >= amin);
#pragma unroll
        for (int jc = 0; jc < 2; jc++) {
            int c = lane + 32 * jc;
            float2 t = unpack2(acc[i][jc]);
            float sc = (t.x + t.y) * SCALE_F;
            float wv = 0.0f;
            if (av && c >= amin) { wv = __expf(sc); dloc += wv; }
            if (a < 65) sW[a * 68 + p + c] = wv;   // W col = buffer row
        }
    }
    // tail window col c = 64 (buffer col p+64); always >= amin
    {
        ull k2t = *(const ull*)&sm[OFF_K2P + lane * 134 + (p + 64) * 2];
        float2 kf2 = unpack2(k2t);
#pragma unroll
        for (int i = 0; i < 9; i++) {
            float2 kf = *(const float2*)&k1q[rowi[i] * 64 + lane * 2];
            float t = kf.x * kf2.x + kf.y * kf2.y;
#pragma unroll
            for (int o = 16; o; o >>= 1) t += __shfl_xor_sync(0xFFFFFFFFu, t, o);
            if (lane == 0) {
                int a = a0 + i;
                if (a < 65) {
                    float wv = (a >= amin) ? __expf(t * SCALE_F) : 0.0f;
                    dloc += wv;
                    sW[a * 68 + p + 64] = wv;
                }
            }
        }
    }
#pragma unroll
    for (int o = 16; o; o >>= 1) dloc += __shfl_xor_sync(0xFFFFFFFFu, dloc, o);
    if (lane == 0) sm[OFF_DEN + p * 8 + wa] = dloc;
    __syncwarp();   // W rows of this warp: cross-lane write->read ordering

    // ================= phase 4: num = sum_r W[a,r] * v2buf[r,:] then v1 fold =====
    ull tmp[9][2];
#pragma unroll
    for (int i = 0; i < 9; i++) { tmp[i][0] = 0ull; tmp[i][1] = 0ull; }

    const float* vb0 = &sm[OFF_V2P + lane * 2];
    const float* vb1 = &sm[OFF_V2P + (lane + 32) * 2];

#pragma unroll 4
    for (int rq = 0; rq < 17; rq++) {
        int rb = rq * 256;               // (2*rq) * 128
        ull vp00 = *(const ull*)(vb0 + rb);
        ull vp01 = *(const ull*)(vb1 + rb);
        ull vp10 = *(const ull*)(vb0 + rb + 128);
        ull vp11 = *(const ull*)(vb1 + rb + 128);
#pragma unroll
        for (int i = 0; i < 9; i++) {
            ulonglong2 wq = *(const ulonglong2*)&sW[(a0 + i) * 68 + rq * 4];
            ffma2(tmp[i][0], wq.x, vp00);
            ffma2(tmp[i][1], wq.x, vp01);
            ffma2(tmp[i][0], wq.y, vp10);
            ffma2(tmp[i][1], wq.y, vp11);
        }
    }

    float ns0 = 0.0f, ns1 = 0.0f;
#pragma unroll
    for (int i = 0; i < 9; i++) {
        float2 t0 = unpack2(tmp[i][0]);
        float2 t1 = unpack2(tmp[i][1]);
        float va = sm[OFF_V1 + rowi[i] * 64 + lane];
        float vb = sm[OFF_V1 + rowi[i] * 64 + lane + 32];
        ns0 += (t0.x + t0.y) * va;       // invalid a rows: W row zero -> tmp zero
        ns1 += (t1.x + t1.y) * vb;
    }
    sm[OFF_NP + (p * 8 + wa) * 64 + lane]      = ns0;
    sm[OFF_NP + (p * 8 + wa) * 64 + lane + 32] = ns1;
    __syncthreads();

    // ================= epilogue =================
    if (tid < P * 64) {
        int pp = tid >> 6, d = tid & 63;
        float den = 1e-8f;
#pragma unroll
        for (int w = 0; w < 8; w++) den += sm[OFF_DEN + pp * 8 + w];
        float num = 0.0f;
#pragma unroll
        for (int w = 0; w < 8; w++) num += sm[OFF_NP + (pp * 8 + w) * 64 + d];
        int o = ((b * Sc + s0 + pp) * Hc + h) * Dc + d;
        out[o] = num / den;
    }
}

extern "C" void kernel_launch(void* const* d_in, const int* in_sizes, int n_in,
                              void* d_out, int out_size) {
    const float* q  = (const float*)d_in[0];
    const float* k1 = (const float*)d_in[1];
    const float* k2 = (const float*)d_in[2];
    const float* v1 = (const float*)d_in[3];
    const float* v2 = (const float*)d_in[4];
    float* out = (float*)d_out;

    cudaFuncSetAttribute(tsa_kernel, cudaFuncAttributeMaxDynamicSharedMemorySize,
                         SMEM_BYTES);
    dim3 grid(Bc * (Sc / P) * Hc);
    tsa_kernel<<<grid, NT, SMEM_BYTES>>>(q, k1, k2, v1, v2, out);
}

// round 4
// speedup vs baseline: 1.2069x; 1.2069x over previous
#include <cuda_runtime.h>

// Two-simplicial attention, B=2, S=2048, H=4, D=64, W1=W2=64 (A=C=65).
// 1 position per CTA, 256 threads, 2 CTAs/SM for latency overlap.

constexpr int Bc = 2, Sc = 2048, Hc = 4, Dc = 64;
constexpr float SCALE_F = 0.125f;
constexpr int NT = 256;

// ---- smem layout (floats) ----
constexpr int OFF_K1Q = 0;                    // [65][64] q-folded k1
constexpr int OFF_K2T = 65 * 64;              // [64][66] k2 transposed [d][window row]
constexpr int OFF_V1  = OFF_K2T + 64 * 66;    // [65][64]
constexpr int OFF_V2  = OFF_V1 + 65 * 64;     // [65][64]
constexpr int OFF_W   = OFF_V2 + 65 * 64;     // [72][66]
constexpr int OFF_NP  = OFF_W + 72 * 66;      // [8][64]
constexpr int OFF_DEN = OFF_NP + 8 * 64;      // [8]
constexpr int SMEM_FLOATS = OFF_DEN + 8;
constexpr int SMEM_BYTES = SMEM_FLOATS * 4;   // ~85.9 KB -> 2 CTAs/SM

typedef unsigned long long ull;

__device__ __forceinline__ void ffma2(ull& acc, ull a, ull b) {
    asm("fma.rn.f32x2 %0, %1, %2, %0;" : "+l"(acc) : "l"(a), "l"(b));
}
__device__ __forceinline__ ull pack2(float lo, float hi) {
    ull r;
    asm("mov.b64 %0, {%1, %2};" : "=l"(r) : "f"(lo), "f"(hi));
    return r;
}
__device__ __forceinline__ float2 unpack2(ull v) {
    float2 f;
    asm("mov.b64 {%0, %1}, %2;" : "=f"(f.x), "=f"(f.y) : "l"(v));
    return f;
}

__global__ void __launch_bounds__(NT, 2)
tsa_kernel(const float* __restrict__ q,
           const float* __restrict__ k1,
           const float* __restrict__ k2,
           const float* __restrict__ v1,
           const float* __restrict__ v2,
           float* __restrict__ out) {
    extern __shared__ float sm[];
    const int tid = threadIdx.x;
    const int bid = blockIdx.x;
    const int h = bid & 3;
    const int s = (bid >> 2) & 2047;
    const int b = bid >> 13;

    // ---- zero W col 64 for rows 65..71 (read in phase 4, never written) ----
    if (tid < 7) sm[OFF_W + (65 + tid) * 66 + 64] = 0.0f;

    // ================= stage A: loads =================
    const int qb = ((b * Sc + s) * Hc + h) * Dc;
    const int dq = tid & 15;                     // fixed per thread (256 % 16 == 0)
    const float4 qv = *(const float4*)&q[qb + dq * 4];

    for (int i = tid; i < 65 * 16; i += NT) {
        int r = i >> 4;
        int g = s - 64 + r; if (g < 0) g = 0;
        int off = ((b * Sc + g) * Hc + h) * Dc + dq * 4;
        *(float4*)&sm[OFF_V1 + r * 64 + dq * 4] = *(const float4*)&v1[off];
        *(float4*)&sm[OFF_V2 + r * 64 + dq * 4] = *(const float4*)&v2[off];
        float4 cv = *(const float4*)&k2[off];
        int d0 = dq * 4;
        sm[OFF_K2T + (d0 + 0) * 66 + r] = cv.x;
        sm[OFF_K2T + (d0 + 1) * 66 + r] = cv.y;
        sm[OFF_K2T + (d0 + 2) * 66 + r] = cv.z;
        sm[OFF_K2T + (d0 + 3) * 66 + r] = cv.w;
        float4 kv = *(const float4*)&k1[off];
        kv.x *= qv.x; kv.y *= qv.y; kv.z *= qv.z; kv.w *= qv.w;
        *(float4*)&sm[OFF_K1Q + r * 64 + d0] = kv;
    }
    __syncthreads();

    // ================= phase 3: scores + exp =================
    const int wid = tid >> 5, lane = tid & 31;
    const int a0 = wid * 9;
    const int amin = 64 - s;

    int rowi[9];
#pragma unroll
    for (int i = 0; i < 9; i++) {
        int r = a0 + i;
        rowi[i] = (r > 64) ? 64 : r;
    }

    ull acc[9][2];
#pragma unroll
    for (int i = 0; i < 9; i++) { acc[i][0] = 0ull; acc[i][1] = 0ull; }

    const float* c0 = &sm[OFF_K2T + lane];
    const float* c1 = &sm[OFF_K2T + lane + 32];

#pragma unroll 4
    for (int dqi = 0; dqi < 16; dqi++) {
        int d0 = dqi * 4;
        float c00 = c0[(d0    ) * 66], c01 = c1[(d0    ) * 66];
        float c10 = c0[(d0 + 1) * 66], c11 = c1[(d0 + 1) * 66];
        float c20 = c0[(d0 + 2) * 66], c21 = c1[(d0 + 2) * 66];
        float c30 = c0[(d0 + 3) * 66], c31 = c1[(d0 + 3) * 66];
        ull kA0 = pack2(c00, c10), kA1 = pack2(c01, c11);
        ull kB0 = pack2(c20, c30), kB1 = pack2(c21, c31);
#pragma unroll
        for (int i = 0; i < 9; i++) {
            ulonglong2 a4 = *(const ulonglong2*)&sm[OFF_K1Q + rowi[i] * 64 + d0];
            ffma2(acc[i][0], a4.x, kA0);
            ffma2(acc[i][1], a4.x, kA1);
            ffma2(acc[i][0], a4.y, kB0);
            ffma2(acc[i][1], a4.y, kB1);
        }
    }

    float dloc = 0.0f;
#pragma unroll
    for (int i = 0; i < 9; i++) {
        int a = a0 + i;
        bool av = (a < 65) && (a >= amin);
#pragma unroll
        for (int jc = 0; jc < 2; jc++) {
            int c = lane + 32 * jc;
            float2 t = unpack2(acc[i][jc]);
            float sc = (t.x + t.y) * SCALE_F;
            float wv = 0.0f;
            if (av && c >= amin) { wv = __expf(sc); dloc += wv; }
            sm[OFF_W + a * 66 + c] = wv;   // rows >= 65 get zeros
        }
    }
    // tail column c = 64 (always >= amin)
    {
        float k2a = sm[OFF_K2T + (2 * lane    ) * 66 + 64];
        float k2b = sm[OFF_K2T + (2 * lane + 1) * 66 + 64];
#pragma unroll
        for (int i = 0; i < 9; i++) {
            float2 kf = *(const float2*)&sm[OFF_K1Q + rowi[i] * 64 + lane * 2];
            float t = kf.x * k2a + kf.y * k2b;
#pragma unroll
            for (int o = 16; o; o >>= 1) t += __shfl_xor_sync(0xFFFFFFFFu, t, o);
            if (lane == 0) {
                int a = a0 + i;
                if (a < 65) {
                    float wv = (a >= amin) ? __expf(t * SCALE_F) : 0.0f;
                    dloc += wv;
                    sm[OFF_W + a * 66 + 64] = wv;
                }
            }
        }
    }
#pragma unroll
    for (int o = 16; o; o >>= 1) dloc += __shfl_xor_sync(0xFFFFFFFFu, dloc, o);
    if (lane == 0) sm[OFF_DEN + wid] = dloc;
    __syncwarp();   // each warp reads only its own W rows below

    // ================= phase 4: num = sum_a v1[a] * (W[a,:] @ V2) =================
    ull tmp[9][2];
#pragma unroll
    for (int i = 0; i < 9; i++) { tmp[i][0] = 0ull; tmp[i][1] = 0ull; }

#pragma unroll 4
    for (int c = 0; c < 64; c += 2) {
        float va0 = sm[OFF_V2 + (c    ) * 64 + lane];
        float va1 = sm[OFF_V2 + (c + 1) * 64 + lane];
        float vb0 = sm[OFF_V2 + (c    ) * 64 + lane + 32];
        float vb1 = sm[OFF_V2 + (c + 1) * 64 + lane + 32];
        ull vp0 = pack2(va0, va1);
        ull vp1 = pack2(vb0, vb1);
#pragma unroll
        for (int i = 0; i < 9; i++) {
            ull wp = *(const ull*)&sm[OFF_W + (a0 + i) * 66 + c];  // broadcast
            ffma2(tmp[i][0], wp, vp0);
            ffma2(tmp[i][1], wp, vp1);
        }
    }
    // tail c = 64 + v1 contraction
    float v64a = sm[OFF_V2 + 64 * 64 + lane];
    float v64b = sm[OFF_V2 + 64 * 64 + lane + 32];
    float ns0 = 0.0f, ns1 = 0.0f;
#pragma unroll
    for (int i = 0; i < 9; i++) {
        float w64 = sm[OFF_W + (a0 + i) * 66 + 64];
        float2 t0 = unpack2(tmp[i][0]);
        float2 t1 = unpack2(tmp[i][1]);
        float ta = t0.x + t0.y + w64 * v64a;
        float tb = t1.x + t1.y + w64 * v64b;
        ta *= sm[OFF_V1 + rowi[i] * 64 + lane];        // invalid rows: all-zero W
        tb *= sm[OFF_V1 + rowi[i] * 64 + lane + 32];
        ns0 += ta;
        ns1 += tb;
    }
    sm[OFF_NP + wid * 64 + lane]      = ns0;
    sm[OFF_NP + wid * 64 + lane + 32] = ns1;
    __syncthreads();

    // ================= epilogue =================
    if (tid < 64) {
        float den = 1e-8f;
#pragma unroll
        for (int w = 0; w < 8; w++) den += sm[OFF_DEN + w];
        float num = 0.0f;
#pragma unroll
        for (int w = 0; w < 8; w++) num += sm[OFF_NP + w * 64 + tid];
        out[qb + tid] = num / den;
    }
}

extern "C" void kernel_launch(void* const* d_in, const int* in_sizes, int n_in,
                              void* d_out, int out_size) {
    const float* q  = (const float*)d_in[0];
    const float* k1 = (const float*)d_in[1];
    const float* k2 = (const float*)d_in[2];
    const float* v1 = (const float*)d_in[3];
    const float* v2 = (const float*)d_in[4];
    float* out = (float*)d_out;

    cudaFuncSetAttribute(tsa_kernel, cudaFuncAttributeMaxDynamicSharedMemorySize,
                         SMEM_BYTES);
    dim3 grid(Bc * Sc * Hc);
    tsa_kernel<<<grid, NT, SMEM_BYTES>>>(q, k1, k2, v1, v2, out);
}